// round 15
// baseline (speedup 1.0000x reference)
#include <cuda_runtime.h>
#include <cuda_fp16.h>
#include <math.h>
#include <stdint.h>

#define B_  4
#define S_  8192
#define D_  1024
#define NF_ 256
#define TWO_NF_ 512
#define M_  (B_*S_)

#define FIR_L 64
#define FIR_W 32

// ---- fp16 tile geometry, BK=32 ----
#define PITCH 80
#define MAT_BYTES (128 * PITCH)               // 10240 (128-row fp16 matrix)

// ---- GEMM1 (BM=64): A fp32 64 rows pitch 160, B fp16 128 rows pitch 80 ----
#define APITCH 160
#define A32_BYTES (64 * APITCH)               // 10240
#define STAGE1_BYTES (A32_BYTES + MAT_BYTES)  // 20480
#define SMEM1_TOTAL (2 * STAGE1_BYTES)        // 40960

// ---- GEMM2 (BM=64): A fp16 64 rows pitch 80, B fp16 128 rows pitch 80 ----
#define A16_BYTES (64 * PITCH)                // 5120
#define STAGE2_BYTES (A16_BYTES + MAT_BYTES)  // 15360
#define SMEM2_TOTAL (2 * STAGE2_BYTES)        // 30720

// ------------------------------ scratch (device globals; no allocs) --------
__device__ __align__(16) unsigned short g_spec[(size_t)M_ * TWO_NF_];  // fp16 spectral
__device__ __align__(16) unsigned short g_wih[(size_t)TWO_NF_ * D_];   // fp16(W_in)
__device__ __align__(16) unsigned short g_woh[(size_t)D_ * TWO_NF_];   // fp16(W_out)
__device__ __align__(16) unsigned short g_fh[(size_t)M_ * TWO_NF_];    // fp16(feats)

// ------------------------------ helpers ------------------------------------
__device__ __forceinline__ uint32_t smem_to_u32(const void* p) {
    uint32_t a;
    asm("{ .reg .u64 t; cvta.to.shared.u64 t, %1; cvt.u32.u64 %0, t; }"
        : "=r"(a) : "l"(p));
    return a;
}

__device__ __forceinline__ void cpa16(uint32_t s, const void* g) {
    asm volatile("cp.async.cg.shared.global [%0], [%1], 16;"
                 :: "r"(s), "l"(g));
}
#define CP_COMMIT()  asm volatile("cp.async.commit_group;" ::: "memory")
#define CP_WAIT1()   asm volatile("cp.async.wait_group 1;" ::: "memory")

__device__ __forceinline__ void ldsm4(uint32_t* r, uint32_t addr) {
    asm volatile("ldmatrix.sync.aligned.m8n8.x4.shared.b16 {%0,%1,%2,%3}, [%4];"
                 : "=r"(r[0]), "=r"(r[1]), "=r"(r[2]), "=r"(r[3]) : "r"(addr));
}

__device__ __forceinline__ void mma16816(float* d, const uint32_t* a,
                                         uint32_t b0, uint32_t b1) {
    asm volatile(
        "mma.sync.aligned.m16n8k16.row.col.f32.f16.f16.f32 "
        "{%0,%1,%2,%3}, {%4,%5,%6,%7}, {%8,%9}, {%0,%1,%2,%3};"
        : "+f"(d[0]), "+f"(d[1]), "+f"(d[2]), "+f"(d[3])
        : "r"(a[0]), "r"(a[1]), "r"(a[2]), "r"(a[3]), "r"(b0), "r"(b1));
}

__device__ __forceinline__ uint32_t pack2h(float a, float b) {
    __half2 h = __floats2half2_rn(a, b);
    return *reinterpret_cast<uint32_t*>(&h);
}

// ---------------------------------------------------------------------------
// GEMM1: C[M,N](fp16) = A32[M,K](fp32, cp.async + in-register cvt) * B^T(fp16)
// BM=64, BN=128, BK=32. 128 threads, 4 warps (2m x 2n), warp tile 32x64.
// ---------------------------------------------------------------------------
__global__ __launch_bounds__(128, 4)
void gemm1_f32a(const float* __restrict__ A32,
                const unsigned short* __restrict__ Bh,
                unsigned short* __restrict__ Ch, int N, int K)
{
    extern __shared__ char smem[];
    const uint32_t sbase = smem_to_u32(smem);

    const int tid  = threadIdx.x;
    const int lane = tid & 31;
    const int wid  = tid >> 5;
    const int wm   = wid >> 1;
    const int wn   = wid & 1;
    const int bm = blockIdx.y * 64;
    const int bn = blockIdx.x * 128;
    const int nchunks = K >> 5;

    const uint32_t lm_off = (uint32_t)(lane & 15) * PITCH + (uint32_t)(lane >> 4) * 16;

    float acc[2][8][4];
#pragma unroll
    for (int i = 0; i < 2; i++)
#pragma unroll
        for (int j = 0; j < 8; j++)
#pragma unroll
            for (int k = 0; k < 4; k++) acc[i][j][k] = 0.0f;

    auto load_A = [&](int c, int buf) {
        const uint32_t sb = sbase + buf * STAGE1_BYTES;
        const int kofs = c * 32;
#pragma unroll
        for (int t = 0; t < 4; t++) {
            const int idx = tid + t * 128;
            const int r = idx >> 3;
            const int sg = idx & 7;
            cpa16(sb + (uint32_t)r * APITCH + sg * 16,
                  A32 + (size_t)(bm + r) * K + kofs + sg * 4);
        }
    };
    auto load_B = [&](int c, int buf) {
        const uint32_t sb = sbase + buf * STAGE1_BYTES + A32_BYTES;
        const int kofs = c * 32;
#pragma unroll
        for (int t = 0; t < 4; t++) {
            const int idx = tid + t * 128;
            const int r = idx >> 2;
            const int sg = idx & 3;
            cpa16(sb + (uint32_t)r * PITCH + sg * 16,
                  Bh + (size_t)(bn + r) * K + kofs + sg * 8);
        }
    };

    load_A(0, 0); load_B(0, 0); CP_COMMIT();
    if (nchunks > 1) { load_A(1, 1); load_B(1, 1); }
    CP_COMMIT();

    const uint32_t aoff = (uint32_t)(wm * 32 + (lane >> 2)) * APITCH
                        + (uint32_t)(lane & 3) * 8;

    for (int c = 0; c < nchunks; c++) {
        const int buf = c & 1;
        CP_WAIT1();
        __syncthreads();

        const char* sA = smem + buf * STAGE1_BYTES;
        const uint32_t bBase = sbase + buf * STAGE1_BYTES + A32_BYTES
                             + (uint32_t)(wn * 64) * PITCH + lm_off;

#pragma unroll
        for (int ks = 0; ks < 2; ks++) {
            const uint32_t ko = ks * 64;
            uint32_t ah[2][4], bh[4][4];
#pragma unroll
            for (int mt = 0; mt < 2; mt++) {
                const char* p = sA + aoff + (uint32_t)(mt * 16) * APITCH + ko;
                float2 v0 = *(const float2*)(p);
                float2 v1 = *(const float2*)(p + 8 * APITCH);
                float2 v2 = *(const float2*)(p + 32);
                float2 v3 = *(const float2*)(p + 8 * APITCH + 32);
                ah[mt][0] = pack2h(v0.x, v0.y);
                ah[mt][1] = pack2h(v1.x, v1.y);
                ah[mt][2] = pack2h(v2.x, v2.y);
                ah[mt][3] = pack2h(v3.x, v3.y);
            }
#pragma unroll
            for (int nt = 0; nt < 4; nt++)
                ldsm4(bh[nt], bBase + (uint32_t)(nt * 16) * PITCH + ks * 32);
#pragma unroll
            for (int nt = 0; nt < 4; nt++)
#pragma unroll
                for (int mt = 0; mt < 2; mt++) {
                    mma16816(acc[mt][2 * nt],     ah[mt], bh[nt][0], bh[nt][2]);
                    mma16816(acc[mt][2 * nt + 1], ah[mt], bh[nt][1], bh[nt][3]);
                }
        }
        __syncthreads();
        if (c + 2 < nchunks) { load_A(c + 2, buf); load_B(c + 2, buf); }
        CP_COMMIT();
    }

    const int r0 = bm + wm * 32 + (lane >> 2);
    const int c0 = bn + wn * 64 + (lane & 3) * 2;
#pragma unroll
    for (int mt = 0; mt < 2; mt++) {
#pragma unroll
        for (int nt = 0; nt < 8; nt++) {
            const int row = r0 + mt * 16;
            const int col = c0 + nt * 8;
            *(uint32_t*)&Ch[(size_t)row * N + col] =
                pack2h(acc[mt][nt][0], acc[mt][nt][1]);
            *(uint32_t*)&Ch[(size_t)(row + 8) * N + col] =
                pack2h(acc[mt][nt][2], acc[mt][nt][3]);
        }
    }
}

// ---------------------------------------------------------------------------
// GEMM2: C[M,N](fp32) = A[M,K](fp16) * B[N,K]^T(fp16)
// BM=64, BN=128, BK=32. 128 threads, 4 warps (2m x 2n), warp tile 32x64.
// ---------------------------------------------------------------------------
__global__ __launch_bounds__(128, 4)
void gemm_mma(const unsigned short* __restrict__ Ah,
              const unsigned short* __restrict__ Bh,
              float* __restrict__ C, int N, int K)
{
    extern __shared__ char smem[];
    const uint32_t sbase = smem_to_u32(smem);

    const int tid  = threadIdx.x;
    const int lane = tid & 31;
    const int wid  = tid >> 5;
    const int wm   = wid >> 1;
    const int wn   = wid & 1;
    const int bm = blockIdx.y * 64;
    const int bn = blockIdx.x * 128;
    const int nchunks = K >> 5;

    const uint32_t lm_off = (uint32_t)(lane & 15) * PITCH + (uint32_t)(lane >> 4) * 16;

    float acc[2][8][4];
#pragma unroll
    for (int i = 0; i < 2; i++)
#pragma unroll
        for (int j = 0; j < 8; j++)
#pragma unroll
            for (int k = 0; k < 4; k++) acc[i][j][k] = 0.0f;

    auto load_stage = [&](int c, int buf) {
        const uint32_t sb = sbase + buf * STAGE2_BYTES;
        const int kofs = c * 32;
        // A: 64 rows x 4 segs = 256; 2 per thread
#pragma unroll
        for (int t = 0; t < 2; t++) {
            const int idx = tid + t * 128;
            const int r = idx >> 2;
            const int sg = idx & 3;
            cpa16(sb + (uint32_t)r * PITCH + sg * 16,
                  Ah + (size_t)(bm + r) * K + kofs + sg * 8);
        }
        // B: 128 rows x 4 segs = 512; 4 per thread
#pragma unroll
        for (int t = 0; t < 4; t++) {
            const int idx = tid + t * 128;
            const int r = idx >> 2;
            const int sg = idx & 3;
            cpa16(sb + A16_BYTES + (uint32_t)r * PITCH + sg * 16,
                  Bh + (size_t)(bn + r) * K + kofs + sg * 8);
        }
    };

    load_stage(0, 0); CP_COMMIT();
    if (nchunks > 1) load_stage(1, 1);
    CP_COMMIT();

    for (int c = 0; c < nchunks; c++) {
        const int buf = c & 1;
        CP_WAIT1();
        __syncthreads();

        const uint32_t sb = sbase + buf * STAGE2_BYTES;
        const uint32_t aBase = sb + (uint32_t)(wm * 32) * PITCH + lm_off;
        const uint32_t bBase = sb + A16_BYTES + (uint32_t)(wn * 64) * PITCH + lm_off;

#pragma unroll
        for (int ks = 0; ks < 2; ks++) {
            const uint32_t ko = ks * 32;
            uint32_t ah[2][4], bh[4][4];
#pragma unroll
            for (int mt = 0; mt < 2; mt++)
                ldsm4(ah[mt], aBase + (uint32_t)(mt * 16) * PITCH + ko);
#pragma unroll
            for (int nt = 0; nt < 4; nt++)
                ldsm4(bh[nt], bBase + (uint32_t)(nt * 16) * PITCH + ko);
#pragma unroll
            for (int nt = 0; nt < 4; nt++)
#pragma unroll
                for (int mt = 0; mt < 2; mt++) {
                    mma16816(acc[mt][2 * nt],     ah[mt], bh[nt][0], bh[nt][2]);
                    mma16816(acc[mt][2 * nt + 1], ah[mt], bh[nt][1], bh[nt][3]);
                }
        }
        __syncthreads();
        if (c + 2 < nchunks) load_stage(c + 2, buf);
        CP_COMMIT();
    }

    const int r0 = bm + wm * 32 + (lane >> 2);
    const int c0 = bn + wn * 64 + (lane & 3) * 2;
#pragma unroll
    for (int mt = 0; mt < 2; mt++) {
#pragma unroll
        for (int nt = 0; nt < 8; nt++) {
            const int row = r0 + mt * 16;
            const int col = c0 + nt * 8;
            *(float2*)&C[(size_t)row * N + col] =
                make_float2(acc[mt][nt][0], acc[mt][nt][1]);
            *(float2*)&C[(size_t)(row + 8) * N + col] =
                make_float2(acc[mt][nt][2], acc[mt][nt][3]);
        }
    }
}

// ---------------------------------------------------------------------------
// both weight conversions in one launch
// ---------------------------------------------------------------------------
__global__ __launch_bounds__(256)
void cvt_weights(const float* __restrict__ w_in, unsigned short* __restrict__ wih,
                 const float* __restrict__ w_out, unsigned short* __restrict__ woh,
                 int n4_each)
{
    int i = blockIdx.x * blockDim.x + threadIdx.x;
    const float* src;
    unsigned short* dst;
    int j;
    if (i < n4_each) { src = w_in; dst = wih; j = i; }
    else             { src = w_out; dst = woh; j = i - n4_each; }
    if (j >= n4_each) return;
    float4 v = ((const float4*)src)[j];
    ushort4 H;
    H.x = __half_as_ushort(__float2half_rn(v.x));
    H.y = __half_as_ushort(__float2half_rn(v.y));
    H.z = __half_as_ushort(__float2half_rn(v.z));
    H.w = __half_as_ushort(__float2half_rn(v.w));
    ((ushort4*)dst)[j] = H;
}

// ---------------------------------------------------------------------------
// FIR: chunked exact linear recurrence h[t] = A*h[t-1] + u[t], y = rot*h.
// |A| = sigmoid(log_decay) < 0.5 -> 32-step warm-up tail <= 0.5^32 ~ 2e-10.
// ---------------------------------------------------------------------------
__global__ __launch_bounds__(NF_)
void fir_kernel(const unsigned short* __restrict__ spec,
                const float* __restrict__ log_decay,
                const float* __restrict__ frequencies,
                unsigned short* __restrict__ fh)
{
    const int f = threadIdx.x;
    const int chunks_per_b = S_ / FIR_L;
    const int b = blockIdx.x / chunks_per_b;
    const int c = blockIdx.x % chunks_per_b;
    const int t_start = c * FIR_L;

    const float ld = log_decay[f];
    const float decay = 1.0f / (1.0f + expf(-ld));
    const float om = frequencies[f] * 0.1f;
    float si, co;
    sincosf(om, &si, &co);
    const float Ar = decay * co;
    const float Ai = decay * si;

    float hr = 0.0f, hi = 0.0f;
    int t0 = t_start - FIR_W;
    if (t0 < 0) t0 = 0;

    const size_t base = (size_t)b * S_ * TWO_NF_;
    const __half* sp = (const __half*)spec;

    for (int t = t0; t < t_start; t++) {               // warm-up
        const size_t row = base + (size_t)t * TWO_NF_;
        const float ur = __half2float(sp[row + f]);
        const float ui = __half2float(sp[row + NF_ + f]);
        const float nhr = fmaf(Ar, hr, fmaf(-Ai, hi, ur));
        const float nhi = fmaf(Ar, hi, fmaf(Ai, hr, ui));
        hr = nhr; hi = nhi;
    }
    for (int t = t_start; t < t_start + FIR_L; t++) {  // output
        const size_t row = base + (size_t)t * TWO_NF_;
        const float ur = __half2float(sp[row + f]);
        const float ui = __half2float(sp[row + NF_ + f]);
        const float nhr = fmaf(Ar, hr, fmaf(-Ai, hi, ur));
        const float nhi = fmaf(Ar, hi, fmaf(Ai, hr, ui));
        hr = nhr; hi = nhi;
        const float yr = fmaf(co, hr, -(si * hi));
        const float yi = fmaf(co, hi,  (si * hr));
        fh[row + f]       = __half_as_ushort(__float2half_rn(yr));
        fh[row + NF_ + f] = __half_as_ushort(__float2half_rn(yi));
    }
}

// ---------------------------------------------------------------------------
extern "C" void kernel_launch(void* const* d_in, const int* in_sizes, int n_in,
                              void* d_out, int out_size) {
    const float* x     = (const float*)d_in[0];   // [B,S,D]
    const float* W_in  = (const float*)d_in[1];   // [2NF, D]
    const float* W_out = (const float*)d_in[2];   // [D, 2NF]
    const float* ldec  = (const float*)d_in[3];   // [NF]
    const float* freqs = (const float*)d_in[4];   // [NF]
    float* out = (float*)d_out;                   // [B,S,D]

    unsigned short *spec, *wih, *woh, *fh;
    cudaGetSymbolAddress((void**)&spec, g_spec);
    cudaGetSymbolAddress((void**)&wih, g_wih);
    cudaGetSymbolAddress((void**)&woh, g_woh);
    cudaGetSymbolAddress((void**)&fh, g_fh);

    cudaFuncSetAttribute(gemm1_f32a, cudaFuncAttributeMaxDynamicSharedMemorySize,
                         SMEM1_TOTAL);
    cudaFuncSetAttribute(gemm_mma, cudaFuncAttributeMaxDynamicSharedMemorySize,
                         SMEM2_TOTAL);

    // 1) weight conversions (single launch)
    {
        int n4 = (TWO_NF_ * D_) / 4;
        cvt_weights<<<(2 * n4 + 255) / 256, 256>>>(W_in, wih, W_out, woh, n4);
    }

    // 2) GEMM1: spec[M, 512](fp16) = x[M,1024](fp32) @ W_in[512,1024]^T
    {
        dim3 grid(TWO_NF_ / 128, M_ / 64);
        gemm1_f32a<<<grid, 128, SMEM1_TOTAL>>>(x, wih, spec, TWO_NF_, D_);
    }

    // 3) FIR scan -> feats (fp16)
    {
        dim3 grid(B_ * (S_ / FIR_L));
        fir_kernel<<<grid, NF_>>>(spec, ldec, freqs, fh);
    }

    // 4) GEMM2: out[M, 1024](fp32) = feats[M,512] @ W_out[1024,512]^T
    {
        dim3 grid(D_ / 128, M_ / 64);
        gemm_mma<<<grid, 128, SMEM2_TOTAL>>>(fh, woh, out, D_, TWO_NF_);
    }
}

// round 16
// speedup vs baseline: 1.0197x; 1.0197x over previous
#include <cuda_runtime.h>
#include <cuda_fp16.h>
#include <math.h>
#include <stdint.h>

#define B_  4
#define S_  8192
#define D_  1024
#define NF_ 256
#define TWO_NF_ 512
#define M_  (B_*S_)

#define FIR_L 64
#define FIR_W 32

// ---- fp16 tile geometry, BK=32 ----
#define PITCH 80
#define MAT_BYTES (128 * PITCH)               // 10240 (128-row fp16 matrix)

// ---- GEMM1 (BM=64): A fp32 64 rows pitch 160, B fp16 128 rows pitch 80 ----
#define APITCH 160
#define A32_BYTES (64 * APITCH)               // 10240
#define STAGE1_BYTES (A32_BYTES + MAT_BYTES)  // 20480
#define SMEM1_TOTAL (2 * STAGE1_BYTES)        // 40960

// ---- GEMM2 (BM=128): A,B fp16 128 rows pitch 80; 3-stage pipeline ----
#define STAGE2_BYTES (2 * MAT_BYTES)          // 20480
#define SMEM2_TOTAL (3 * STAGE2_BYTES)        // 61440

// ------------------------------ scratch (device globals; no allocs) --------
__device__ __align__(16) unsigned short g_spec[(size_t)M_ * TWO_NF_];  // fp16 spectral
__device__ __align__(16) unsigned short g_wih[(size_t)TWO_NF_ * D_];   // fp16(W_in)
__device__ __align__(16) unsigned short g_woh[(size_t)D_ * TWO_NF_];   // fp16(W_out)
__device__ __align__(16) unsigned short g_fh[(size_t)M_ * TWO_NF_];    // fp16(feats)

// ------------------------------ helpers ------------------------------------
__device__ __forceinline__ uint32_t smem_to_u32(const void* p) {
    uint32_t a;
    asm("{ .reg .u64 t; cvta.to.shared.u64 t, %1; cvt.u32.u64 %0, t; }"
        : "=r"(a) : "l"(p));
    return a;
}

__device__ __forceinline__ void cpa16(uint32_t s, const void* g) {
    asm volatile("cp.async.cg.shared.global [%0], [%1], 16;"
                 :: "r"(s), "l"(g));
}
#define CP_COMMIT()  asm volatile("cp.async.commit_group;" ::: "memory")
#define CP_WAIT1()   asm volatile("cp.async.wait_group 1;" ::: "memory")
#define CP_WAIT2()   asm volatile("cp.async.wait_group 2;" ::: "memory")

__device__ __forceinline__ void ldsm4(uint32_t* r, uint32_t addr) {
    asm volatile("ldmatrix.sync.aligned.m8n8.x4.shared.b16 {%0,%1,%2,%3}, [%4];"
                 : "=r"(r[0]), "=r"(r[1]), "=r"(r[2]), "=r"(r[3]) : "r"(addr));
}

__device__ __forceinline__ void mma16816(float* d, const uint32_t* a,
                                         uint32_t b0, uint32_t b1) {
    asm volatile(
        "mma.sync.aligned.m16n8k16.row.col.f32.f16.f16.f32 "
        "{%0,%1,%2,%3}, {%4,%5,%6,%7}, {%8,%9}, {%0,%1,%2,%3};"
        : "+f"(d[0]), "+f"(d[1]), "+f"(d[2]), "+f"(d[3])
        : "r"(a[0]), "r"(a[1]), "r"(a[2]), "r"(a[3]), "r"(b0), "r"(b1));
}

__device__ __forceinline__ uint32_t pack2h(float a, float b) {
    __half2 h = __floats2half2_rn(a, b);
    return *reinterpret_cast<uint32_t*>(&h);
}

// ---------------------------------------------------------------------------
// GEMM1: C[M,N](fp16) = A32[M,K](fp32, cp.async + in-register cvt) * B^T(fp16)
// BM=64, BN=128, BK=32. 128 threads, 4 warps (2m x 2n).  [R14 exact]
// ---------------------------------------------------------------------------
__global__ __launch_bounds__(128, 4)
void gemm1_f32a(const float* __restrict__ A32,
                const unsigned short* __restrict__ Bh,
                unsigned short* __restrict__ Ch, int N, int K)
{
    extern __shared__ char smem[];
    const uint32_t sbase = smem_to_u32(smem);

    const int tid  = threadIdx.x;
    const int lane = tid & 31;
    const int wid  = tid >> 5;
    const int wm   = wid >> 1;
    const int wn   = wid & 1;
    const int bm = blockIdx.y * 64;
    const int bn = blockIdx.x * 128;
    const int nchunks = K >> 5;

    const uint32_t lm_off = (uint32_t)(lane & 15) * PITCH + (uint32_t)(lane >> 4) * 16;

    float acc[2][8][4];
#pragma unroll
    for (int i = 0; i < 2; i++)
#pragma unroll
        for (int j = 0; j < 8; j++)
#pragma unroll
            for (int k = 0; k < 4; k++) acc[i][j][k] = 0.0f;

    auto load_A = [&](int c, int buf) {
        const uint32_t sb = sbase + buf * STAGE1_BYTES;
        const int kofs = c * 32;
#pragma unroll
        for (int t = 0; t < 4; t++) {
            const int idx = tid + t * 128;
            const int r = idx >> 3;
            const int sg = idx & 7;
            cpa16(sb + (uint32_t)r * APITCH + sg * 16,
                  A32 + (size_t)(bm + r) * K + kofs + sg * 4);
        }
    };
    auto load_B = [&](int c, int buf) {
        const uint32_t sb = sbase + buf * STAGE1_BYTES + A32_BYTES;
        const int kofs = c * 32;
#pragma unroll
        for (int t = 0; t < 4; t++) {
            const int idx = tid + t * 128;
            const int r = idx >> 2;
            const int sg = idx & 3;
            cpa16(sb + (uint32_t)r * PITCH + sg * 16,
                  Bh + (size_t)(bn + r) * K + kofs + sg * 8);
        }
    };

    load_A(0, 0); load_B(0, 0); CP_COMMIT();
    if (nchunks > 1) { load_A(1, 1); load_B(1, 1); }
    CP_COMMIT();

    const uint32_t aoff = (uint32_t)(wm * 32 + (lane >> 2)) * APITCH
                        + (uint32_t)(lane & 3) * 8;

    for (int c = 0; c < nchunks; c++) {
        const int buf = c & 1;
        CP_WAIT1();
        __syncthreads();

        const char* sA = smem + buf * STAGE1_BYTES;
        const uint32_t bBase = sbase + buf * STAGE1_BYTES + A32_BYTES
                             + (uint32_t)(wn * 64) * PITCH + lm_off;

#pragma unroll
        for (int ks = 0; ks < 2; ks++) {
            const uint32_t ko = ks * 64;
            uint32_t ah[2][4], bh[4][4];
#pragma unroll
            for (int mt = 0; mt < 2; mt++) {
                const char* p = sA + aoff + (uint32_t)(mt * 16) * APITCH + ko;
                float2 v0 = *(const float2*)(p);
                float2 v1 = *(const float2*)(p + 8 * APITCH);
                float2 v2 = *(const float2*)(p + 32);
                float2 v3 = *(const float2*)(p + 8 * APITCH + 32);
                ah[mt][0] = pack2h(v0.x, v0.y);
                ah[mt][1] = pack2h(v1.x, v1.y);
                ah[mt][2] = pack2h(v2.x, v2.y);
                ah[mt][3] = pack2h(v3.x, v3.y);
            }
#pragma unroll
            for (int nt = 0; nt < 4; nt++)
                ldsm4(bh[nt], bBase + (uint32_t)(nt * 16) * PITCH + ks * 32);
#pragma unroll
            for (int nt = 0; nt < 4; nt++)
#pragma unroll
                for (int mt = 0; mt < 2; mt++) {
                    mma16816(acc[mt][2 * nt],     ah[mt], bh[nt][0], bh[nt][2]);
                    mma16816(acc[mt][2 * nt + 1], ah[mt], bh[nt][1], bh[nt][3]);
                }
        }
        __syncthreads();
        if (c + 2 < nchunks) { load_A(c + 2, buf); load_B(c + 2, buf); }
        CP_COMMIT();
    }

    const int r0 = bm + wm * 32 + (lane >> 2);
    const int c0 = bn + wn * 64 + (lane & 3) * 2;
#pragma unroll
    for (int mt = 0; mt < 2; mt++) {
#pragma unroll
        for (int nt = 0; nt < 8; nt++) {
            const int row = r0 + mt * 16;
            const int col = c0 + nt * 8;
            *(uint32_t*)&Ch[(size_t)row * N + col] =
                pack2h(acc[mt][nt][0], acc[mt][nt][1]);
            *(uint32_t*)&Ch[(size_t)(row + 8) * N + col] =
                pack2h(acc[mt][nt][2], acc[mt][nt][3]);
        }
    }
}

// ---------------------------------------------------------------------------
// GEMM2: C[M,N](fp32) = A[M,K](fp16) * B[N,K]^T(fp16)
// BM=128, BN=128, BK=32, 256 threads. 3-stage cp.async pipeline.
// ---------------------------------------------------------------------------
__global__ __launch_bounds__(256, 2)
void gemm_mma(const unsigned short* __restrict__ Ah,
              const unsigned short* __restrict__ Bh,
              float* __restrict__ C, int N, int K)
{
    extern __shared__ char smem[];
    const uint32_t sbase = smem_to_u32(smem);

    const int tid  = threadIdx.x;
    const int lane = tid & 31;
    const int wid  = tid >> 5;
    const int wm   = wid >> 1;
    const int wn   = wid & 1;
    const int bm = blockIdx.y * 128;
    const int bn = blockIdx.x * 128;
    const int nchunks = K >> 5;      // 16

    const uint32_t lm_off = (uint32_t)(lane & 15) * PITCH + (uint32_t)(lane >> 4) * 16;

    float acc[2][8][4];
#pragma unroll
    for (int i = 0; i < 2; i++)
#pragma unroll
        for (int j = 0; j < 8; j++)
#pragma unroll
            for (int k = 0; k < 4; k++) acc[i][j][k] = 0.0f;

    auto load_stage = [&](int c, int buf) {
        const uint32_t sb = sbase + buf * STAGE2_BYTES;
        const int kofs = c * 32;
#pragma unroll
        for (int t = 0; t < 2; t++) {
            const int idx = tid + t * 256;
            const int r = idx >> 2;
            const int sg = idx & 3;
            const uint32_t so = (uint32_t)r * PITCH + sg * 16;
            cpa16(sb + 0 * MAT_BYTES + so, Ah + (size_t)(bm + r) * K + kofs + sg * 8);
            cpa16(sb + 1 * MAT_BYTES + so, Bh + (size_t)(bn + r) * K + kofs + sg * 8);
        }
    };

    // prologue: fill 3 stages
    load_stage(0, 0); CP_COMMIT();
    load_stage(1, 1); CP_COMMIT();
    load_stage(2, 2); CP_COMMIT();

    int buf = 0;
    for (int c = 0; c < nchunks; c++) {
        CP_WAIT2();                 // stage c landed (<=2 groups pending)
        __syncthreads();

        const uint32_t sb = sbase + buf * STAGE2_BYTES;
        const uint32_t aBase = sb + (uint32_t)(wm * 32) * PITCH + lm_off;
        const uint32_t bBase = sb + MAT_BYTES + (uint32_t)(wn * 64) * PITCH + lm_off;

#pragma unroll
        for (int ks = 0; ks < 2; ks++) {
            const uint32_t ko = ks * 32;
            uint32_t ah[2][4], bh[4][4];
#pragma unroll
            for (int mt = 0; mt < 2; mt++)
                ldsm4(ah[mt], aBase + (uint32_t)(mt * 16) * PITCH + ko);
#pragma unroll
            for (int nt = 0; nt < 4; nt++)
                ldsm4(bh[nt], bBase + (uint32_t)(nt * 16) * PITCH + ko);
#pragma unroll
            for (int nt = 0; nt < 4; nt++)
#pragma unroll
                for (int mt = 0; mt < 2; mt++) {
                    mma16816(acc[mt][2 * nt],     ah[mt], bh[nt][0], bh[nt][2]);
                    mma16816(acc[mt][2 * nt + 1], ah[mt], bh[nt][1], bh[nt][3]);
                }
        }
        __syncthreads();            // all warps done with stage c's buffer
        if (c + 3 < nchunks) load_stage(c + 3, buf);
        CP_COMMIT();

        buf = (buf == 2) ? 0 : buf + 1;
    }

    const int r0 = bm + wm * 32 + (lane >> 2);
    const int c0 = bn + wn * 64 + (lane & 3) * 2;
#pragma unroll
    for (int mt = 0; mt < 2; mt++) {
#pragma unroll
        for (int nt = 0; nt < 8; nt++) {
            const int row = r0 + mt * 16;
            const int col = c0 + nt * 8;
            *(float2*)&C[(size_t)row * N + col] =
                make_float2(acc[mt][nt][0], acc[mt][nt][1]);
            *(float2*)&C[(size_t)(row + 8) * N + col] =
                make_float2(acc[mt][nt][2], acc[mt][nt][3]);
        }
    }
}

// ---------------------------------------------------------------------------
// both weight conversions in one launch
// ---------------------------------------------------------------------------
__global__ __launch_bounds__(256)
void cvt_weights(const float* __restrict__ w_in, unsigned short* __restrict__ wih,
                 const float* __restrict__ w_out, unsigned short* __restrict__ woh,
                 int n4_each)
{
    int i = blockIdx.x * blockDim.x + threadIdx.x;
    const float* src;
    unsigned short* dst;
    int j;
    if (i < n4_each) { src = w_in; dst = wih; j = i; }
    else             { src = w_out; dst = woh; j = i - n4_each; }
    if (j >= n4_each) return;
    float4 v = ((const float4*)src)[j];
    ushort4 H;
    H.x = __half_as_ushort(__float2half_rn(v.x));
    H.y = __half_as_ushort(__float2half_rn(v.y));
    H.z = __half_as_ushort(__float2half_rn(v.z));
    H.w = __half_as_ushort(__float2half_rn(v.w));
    ((ushort4*)dst)[j] = H;
}

// ---------------------------------------------------------------------------
// FIR: chunked exact linear recurrence h[t] = A*h[t-1] + u[t], y = rot*h.
// |A| = sigmoid(log_decay) < 0.5 -> 32-step warm-up tail <= 0.5^32 ~ 2e-10.
// ---------------------------------------------------------------------------
__global__ __launch_bounds__(NF_)
void fir_kernel(const unsigned short* __restrict__ spec,
                const float* __restrict__ log_decay,
                const float* __restrict__ frequencies,
                unsigned short* __restrict__ fh)
{
    const int f = threadIdx.x;
    const int chunks_per_b = S_ / FIR_L;
    const int b = blockIdx.x / chunks_per_b;
    const int c = blockIdx.x % chunks_per_b;
    const int t_start = c * FIR_L;

    const float ld = log_decay[f];
    const float decay = 1.0f / (1.0f + expf(-ld));
    const float om = frequencies[f] * 0.1f;
    float si, co;
    sincosf(om, &si, &co);
    const float Ar = decay * co;
    const float Ai = decay * si;

    float hr = 0.0f, hi = 0.0f;
    int t0 = t_start - FIR_W;
    if (t0 < 0) t0 = 0;

    const size_t base = (size_t)b * S_ * TWO_NF_;
    const __half* sp = (const __half*)spec;

    for (int t = t0; t < t_start; t++) {               // warm-up
        const size_t row = base + (size_t)t * TWO_NF_;
        const float ur = __half2float(sp[row + f]);
        const float ui = __half2float(sp[row + NF_ + f]);
        const float nhr = fmaf(Ar, hr, fmaf(-Ai, hi, ur));
        const float nhi = fmaf(Ar, hi, fmaf(Ai, hr, ui));
        hr = nhr; hi = nhi;
    }
    for (int t = t_start; t < t_start + FIR_L; t++) {  // output
        const size_t row = base + (size_t)t * TWO_NF_;
        const float ur = __half2float(sp[row + f]);
        const float ui = __half2float(sp[row + NF_ + f]);
        const float nhr = fmaf(Ar, hr, fmaf(-Ai, hi, ur));
        const float nhi = fmaf(Ar, hi, fmaf(Ai, hr, ui));
        hr = nhr; hi = nhi;
        const float yr = fmaf(co, hr, -(si * hi));
        const float yi = fmaf(co, hi,  (si * hr));
        fh[row + f]       = __half_as_ushort(__float2half_rn(yr));
        fh[row + NF_ + f] = __half_as_ushort(__float2half_rn(yi));
    }
}

// ---------------------------------------------------------------------------
extern "C" void kernel_launch(void* const* d_in, const int* in_sizes, int n_in,
                              void* d_out, int out_size) {
    const float* x     = (const float*)d_in[0];   // [B,S,D]
    const float* W_in  = (const float*)d_in[1];   // [2NF, D]
    const float* W_out = (const float*)d_in[2];   // [D, 2NF]
    const float* ldec  = (const float*)d_in[3];   // [NF]
    const float* freqs = (const float*)d_in[4];   // [NF]
    float* out = (float*)d_out;                   // [B,S,D]

    unsigned short *spec, *wih, *woh, *fh;
    cudaGetSymbolAddress((void**)&spec, g_spec);
    cudaGetSymbolAddress((void**)&wih, g_wih);
    cudaGetSymbolAddress((void**)&woh, g_woh);
    cudaGetSymbolAddress((void**)&fh, g_fh);

    cudaFuncSetAttribute(gemm1_f32a, cudaFuncAttributeMaxDynamicSharedMemorySize,
                         SMEM1_TOTAL);
    cudaFuncSetAttribute(gemm_mma, cudaFuncAttributeMaxDynamicSharedMemorySize,
                         SMEM2_TOTAL);

    // 1) weight conversions (single launch)
    {
        int n4 = (TWO_NF_ * D_) / 4;
        cvt_weights<<<(2 * n4 + 255) / 256, 256>>>(W_in, wih, W_out, woh, n4);
    }

    // 2) GEMM1: spec[M, 512](fp16) = x[M,1024](fp32) @ W_in[512,1024]^T
    {
        dim3 grid(TWO_NF_ / 128, M_ / 64);
        gemm1_f32a<<<grid, 128, SMEM1_TOTAL>>>(x, wih, spec, TWO_NF_, D_);
    }

    // 3) FIR scan -> feats (fp16)
    {
        dim3 grid(B_ * (S_ / FIR_L));
        fir_kernel<<<grid, NF_>>>(spec, ldec, freqs, fh);
    }

    // 4) GEMM2: out[M, 1024](fp32) = feats[M,512] @ W_out[1024,512]^T
    {
        dim3 grid(D_ / 128, M_ / 128);
        gemm_mma<<<grid, 256, SMEM2_TOTAL>>>(fh, woh, out, D_, TWO_NF_);
    }
}